// round 9
// baseline (speedup 1.0000x reference)
#include <cuda_runtime.h>
#include <cstdint>

// Problem constants
#define CB_K     512
#define CB_HALF  256
#define EMB_D    64
#define N_ROWS   65536
#define Q_ELEMS  ((size_t)N_ROWS * EMB_D)

// Phase-1: 128 threads, 2 rows/thread, half codebook per CTA
#define P1_THREADS 128
#define ROWS_PER_CTA 256                 // 128 thr * 2 rows
#define N_RB   (N_ROWS / ROWS_PER_CTA)   // 256 row-blocks
#define P1_CTAS (N_RB * 2)               // 512 (x2 halves)

// Phase-1 smem: half codebook [256][64] + sc[256]
#define P1_SMEM_FLOATS (CB_HALF * EMB_D + CB_HALF)
#define P1_SMEM_BYTES  (P1_SMEM_FLOATS * 4)

// Phase-2: one thread per row
#define P2_THREADS 256
#define P2_CTAS    (N_ROWS / P2_THREADS)  // 256

__device__ float g_best[2 * N_ROWS];     // per-half best distance
__device__ int   g_idx [2 * N_ROWS];     // per-half best index (global code id)
__device__ float g_partial[P2_CTAS];     // per-CTA SSE partials (phase 2)

// ---- packed f32x2 helpers (force FFMA2 in SASS) ----
__device__ __forceinline__ unsigned long long fma2(unsigned long long a,
                                                   unsigned long long b,
                                                   unsigned long long c) {
    unsigned long long r;
    asm("fma.rn.f32x2 %0, %1, %2, %3;" : "=l"(r) : "l"(a), "l"(b), "l"(c));
    return r;
}
__device__ __forceinline__ unsigned long long add2(unsigned long long a,
                                                   unsigned long long b) {
    unsigned long long r;
    asm("add.rn.f32x2 %0, %1, %2;" : "=l"(r) : "l"(a), "l"(b));
    return r;
}
__device__ __forceinline__ unsigned long long pk2(float lo, float hi) {
    unsigned long long r;
    asm("mov.b64 %0, {%1, %2};" : "=l"(r) : "f"(lo), "f"(hi));
    return r;
}
__device__ __forceinline__ float lo2(unsigned long long v) {
    return __uint_as_float((unsigned)(v & 0xffffffffull));
}
__device__ __forceinline__ float hi2(unsigned long long v) {
    return __uint_as_float((unsigned)(v >> 32));
}

// Phase 1: each CTA = (row-block, codebook-half). 3 CTAs/SM -> 3 warps/SMSP.
// Numerics of d_k identical to the R8 kernel (same chains, same association).
__global__ void __launch_bounds__(P1_THREADS, 3)
vq_half_kernel(const float* __restrict__ x_g,
               const float* __restrict__ e_g) {
    extern __shared__ float smem[];
    float* se = smem;                     // [256][64] half codebook
    float* sc = smem + CB_HALF * EMB_D;   // [256] |e_k|^2

    const int tid  = threadIdx.x;
    const int cid  = blockIdx.x;
    const int half = cid & 1;             // 0: codes 0-255, 1: codes 256-511
    const int rb   = cid >> 1;            // row-block 0..255
    const int kbase = half * CB_HALF;

    // --- stage half codebook into smem (coalesced float4) ---
    {
        float4* se4 = reinterpret_cast<float4*>(se);
        const float4* eg4 = reinterpret_cast<const float4*>(e_g) +
                            (size_t)kbase * (EMB_D / 4);
        #pragma unroll
        for (int i = 0; i < (CB_HALF * EMB_D / 4) / P1_THREADS; i++)
            se4[tid + i * P1_THREADS] = eg4[tid + i * P1_THREADS];
    }
    __syncthreads();

    // --- |e_k|^2 (2 codes per thread) ---
    #pragma unroll
    for (int kk = 0; kk < CB_HALF / P1_THREADS; kk++) {
        int k = tid + kk * P1_THREADS;
        const float* er = se + k * EMB_D;
        float s = 0.f;
        #pragma unroll 16
        for (int d = 0; d < EMB_D; d++) s = __fmaf_rn(er[d], er[d], s);
        sc[k] = s;
    }
    __syncthreads();

    // --- load the two x rows into registers as f32x2 pairs ---
    const int row0 = rb * ROWS_PER_CTA + tid;
    const int row1 = row0 + P1_THREADS;
    unsigned long long xa[32], xb[32];
    {
        const float4* xr0 = reinterpret_cast<const float4*>(x_g + (size_t)row0 * EMB_D);
        const float4* xr1 = reinterpret_cast<const float4*>(x_g + (size_t)row1 * EMB_D);
        #pragma unroll
        for (int i = 0; i < 16; i++) {
            float4 f = xr0[i];
            xa[2 * i]     = pk2(f.x, f.y);
            xa[2 * i + 1] = pk2(f.z, f.w);
            float4 g = xr1[i];
            xb[2 * i]     = pk2(g.x, g.y);
            xb[2 * i + 1] = pk2(g.z, g.w);
        }
    }

    // --- A = |x|^2 per row (same summation tree as R8) ---
    float A0, A1;
    {
        unsigned long long a0 = 0, a1 = 0, a2 = 0, a3 = 0;
        unsigned long long b0 = 0, b1 = 0, b2 = 0, b3 = 0;
        #pragma unroll
        for (int i = 0; i < 32; i += 4) {
            a0 = fma2(xa[i],     xa[i],     a0);
            a1 = fma2(xa[i + 1], xa[i + 1], a1);
            a2 = fma2(xa[i + 2], xa[i + 2], a2);
            a3 = fma2(xa[i + 3], xa[i + 3], a3);
            b0 = fma2(xb[i],     xb[i],     b0);
            b1 = fma2(xb[i + 1], xb[i + 1], b1);
            b2 = fma2(xb[i + 2], xb[i + 2], b2);
            b3 = fma2(xb[i + 3], xb[i + 3], b3);
        }
        unsigned long long s0 = add2(add2(a0, a2), add2(a1, a3));
        unsigned long long s1 = add2(add2(b0, b2), add2(b1, b3));
        A0 = lo2(s0) + hi2(s0);
        A1 = lo2(s1) + hi2(s1);
    }

    // --- argmin over this half's 256 codes (exact R8 loop body) ---
    float best0 = 3.4e38f, best1 = 3.4e38f;
    int   bk0   = 0,       bk1   = 0;
    const ulonglong2* seu = reinterpret_cast<const ulonglong2*>(se);
    #pragma unroll 2
    for (int k = 0; k < CB_HALF; k++) {
        const ulonglong2* ek = seu + k * 16;
        unsigned long long a0 = 0, a1 = 0, a2 = 0, a3 = 0;
        unsigned long long b0 = 0, b1 = 0, b2 = 0, b3 = 0;
        #pragma unroll
        for (int i = 0; i < 16; i += 2) {
            ulonglong2 e0 = ek[i];
            ulonglong2 e1 = ek[i + 1];
            a0 = fma2(xa[2 * i],     e0.x, a0);
            a1 = fma2(xa[2 * i + 1], e0.y, a1);
            a2 = fma2(xa[2 * i + 2], e1.x, a2);
            a3 = fma2(xa[2 * i + 3], e1.y, a3);
            b0 = fma2(xb[2 * i],     e0.x, b0);
            b1 = fma2(xb[2 * i + 1], e0.y, b1);
            b2 = fma2(xb[2 * i + 2], e1.x, b2);
            b3 = fma2(xb[2 * i + 3], e1.y, b3);
        }
        float ck = sc[k];
        unsigned long long s0 = add2(add2(a0, a2), add2(a1, a3));
        unsigned long long s1 = add2(add2(b0, b2), add2(b1, b3));
        float dot0 = lo2(s0) + hi2(s0);
        float dot1 = lo2(s1) + hi2(s1);
        // 2*dot exact -> fmaf(-2,dot,A) == fl(A - 2*dot) bit-for-bit
        float dd0 = __fadd_rn(__fmaf_rn(-2.0f, dot0, A0), ck);
        float dd1 = __fadd_rn(__fmaf_rn(-2.0f, dot1, A1), ck);
        if (dd0 < best0) { best0 = dd0; bk0 = k; }   // strict < -> lowest k on ties
        if (dd1 < best1) { best1 = dd1; bk1 = k; }
    }

    // --- write per-half results ---
    const size_t base = (size_t)half * N_ROWS;
    g_best[base + row0] = best0;
    g_best[base + row1] = best1;
    g_idx [base + row0] = kbase + bk0;
    g_idx [base + row1] = kbase + bk1;
}

// Phase 2: one thread per row. Merge halves (tie -> lower half = lower index,
// matching ascending-k strict-< semantics), gather e[bk] from L2, write
// quantized row + index, accumulate SSE.
__global__ void __launch_bounds__(P2_THREADS)
vq_merge_kernel(const float* __restrict__ x_g,
                const float* __restrict__ e_g,
                float* __restrict__ out) {
    __shared__ float sred[P2_THREADS];
    const int tid = threadIdx.x;
    const int row = blockIdx.x * P2_THREADS + tid;

    float bP = g_best[row];
    float bQ = g_best[N_ROWS + row];
    int   iP = g_idx[row];
    int   iQ = g_idx[N_ROWS + row];
    // reference argmin: lowest index wins ties; P indices < Q indices
    const int bk = (bQ < bP) ? iQ : iP;

    // gather quantized row (codebook stays L2-resident: 128 KB)
    const float4* qe = reinterpret_cast<const float4*>(e_g + (size_t)bk * EMB_D);
    const float4* xr = reinterpret_cast<const float4*>(x_g + (size_t)row * EMB_D);
    float q[64];
    float sse = 0.f;
    #pragma unroll
    for (int i = 0; i < 16; i++) {
        float4 qq = qe[i];
        float4 xx = xr[i];
        q[4 * i]     = qq.x; q[4 * i + 1] = qq.y;
        q[4 * i + 2] = qq.z; q[4 * i + 3] = qq.w;
        float d0 = qq.x - xx.x, d1 = qq.y - xx.y;
        float d2 = qq.z - xx.z, d3 = qq.w - xx.w;
        sse = __fmaf_rn(d0, d0, sse);
        sse = __fmaf_rn(d1, d1, sse);
        sse = __fmaf_rn(d2, d2, sse);
        sse = __fmaf_rn(d3, d3, sse);
    }

    // quantized region starts at out+1: peel 3, 15 aligned float4, 1 tail
    float* orow = out + 1 + (size_t)row * EMB_D;
    orow[0] = q[0]; orow[1] = q[1]; orow[2] = q[2];
    float4* ov = reinterpret_cast<float4*>(orow + 3);
    #pragma unroll
    for (int i = 0; i < 15; i++) {
        float4 v;
        v.x = q[3 + 4 * i]; v.y = q[4 + 4 * i];
        v.z = q[5 + 4 * i]; v.w = q[6 + 4 * i];
        ov[i] = v;
    }
    orow[63] = q[63];
    out[1 + Q_ELEMS + (size_t)row] = (float)bk;

    // CTA loss partial (deterministic tree)
    sred[tid] = sse;
    __syncthreads();
    #pragma unroll
    for (int off = P2_THREADS / 2; off > 0; off >>= 1) {
        if (tid < off) sred[tid] = sred[tid] + sred[tid + off];
        __syncthreads();
    }
    if (tid == 0) g_partial[blockIdx.x] = sred[0];
}

// Final deterministic reduce over 256 CTA partials: loss = 1.25 * SSE / (N*D)
__global__ void vq_reduce_kernel(float* __restrict__ out) {
    __shared__ double sd[P2_CTAS];
    int tid = threadIdx.x;
    sd[tid] = (double)g_partial[tid];
    __syncthreads();
    #pragma unroll
    for (int off = P2_CTAS / 2; off > 0; off >>= 1) {
        if (tid < off) sd[tid] = sd[tid] + sd[tid + off];
        __syncthreads();
    }
    if (tid == 0) {
        double mean = sd[0] / (double)((size_t)N_ROWS * EMB_D);
        out[0] = (float)(1.25 * mean);   // q_latent + 0.25 * e_latent
    }
}

extern "C" void kernel_launch(void* const* d_in, const int* in_sizes, int n_in,
                              void* d_out, int out_size) {
    const float* x = (const float*)d_in[0];
    const float* e = (const float*)d_in[1];
    if (n_in >= 2 && in_sizes[0] == CB_K * EMB_D) {
        const float* t = x; x = e; e = t;
    }
    float* out = (float*)d_out;

    cudaFuncSetAttribute(vq_half_kernel,
                         cudaFuncAttributeMaxDynamicSharedMemorySize, P1_SMEM_BYTES);
    vq_half_kernel<<<P1_CTAS, P1_THREADS, P1_SMEM_BYTES>>>(x, e);
    vq_merge_kernel<<<P2_CTAS, P2_THREADS>>>(x, e, out);
    vq_reduce_kernel<<<1, P2_CTAS>>>(out);
}